// round 13
// baseline (speedup 1.0000x reference)
#include <cuda_runtime.h>
#include <cuda_fp16.h>
#include <cstdint>

#define NF   100000
#define CLIP 50
#define D    64
#define NT   13   // friend-slot iterations (4 friends each; 52 slots, 2 padded)
#define PF   4    // software-pipeline depth

// fp16 shadow of emb_user: (NF+1) x 64 halves = 12.8 MB, static device global.
__device__ __half g_emb_h[(size_t)(NF + 1) * D];

// ---- precompute: f32 -> f16 table conversion (8 elems / thread, 16 B stores)
__global__ __launch_bounds__(256)
void conv_kernel(const float* __restrict__ src, int n8)
{
    const int i = blockIdx.x * blockDim.x + threadIdx.x;
    if (i >= n8) return;
    const float4* s = (const float4*)src + 2 * (size_t)i;
    const float4 a = s[0], b = s[1];
    __half2 h0 = __floats2half2_rn(a.x, a.y);
    __half2 h1 = __floats2half2_rn(a.z, a.w);
    __half2 h2 = __floats2half2_rn(b.x, b.y);
    __half2 h3 = __floats2half2_rn(b.z, b.w);
    uint4 p;
    p.x = *reinterpret_cast<unsigned*>(&h0);
    p.y = *reinterpret_cast<unsigned*>(&h1);
    p.z = *reinterpret_cast<unsigned*>(&h2);
    p.w = *reinterpret_cast<unsigned*>(&h3);
    reinterpret_cast<uint4*>(g_emb_h)[i] = p;
}

// 8 lanes per friend (16 B of fp16 row each -> 1 LDG.128 per friend), 4 friends/warp-iter.
// logits = sum_c gate_c * pd_c / nfr  (pd_c = dot(fe_c, ie*w) = pre-sigmoid value)
__global__ __launch_bounds__(256, 4)
void gmf_kernel(const int*   __restrict__ user_indices,
                const int*   __restrict__ item_indices,
                const int*   __restrict__ ufi,          // [100000, 50]
                const float* __restrict__ emb_item,     // [100000, 64]
                const float* __restrict__ affine_w,     // [64]
                const float* __restrict__ affine_b,     // scalar
                float*       __restrict__ rating_out,   // [B]
                float*       __restrict__ gidx_out,     // [B, 50] or null
                int B)
{
    const int warp = (int)((blockIdx.x * blockDim.x + threadIdx.x) >> 5);
    const int lane = threadIdx.x & 31;
    if (warp >= B) return;

    const int lig = lane & 7;    // lane in 8-lane group
    const int grp = lane >> 3;   // friend-group 0..3

    const int   u    = user_indices[warp];
    const int   it   = item_indices[warp];
    const float bias = *affine_b;

    // lane holds dims [8*lig, 8*lig+8) of (item_emb * w)
    float4 iw0, iw1;
    {
        const float4* ie = (const float4*)(emb_item + (size_t)it * D);
        const float4* w  = (const float4*)affine_w;
        float4 a = ie[2 * lig],     b0 = w[2 * lig];
        float4 c = ie[2 * lig + 1], d0 = w[2 * lig + 1];
        iw0 = make_float4(a.x*b0.x, a.y*b0.y, a.z*b0.z, a.w*b0.w);
        iw1 = make_float4(c.x*d0.x, c.y*d0.y, c.z*d0.z, c.w*d0.w);
    }

    const int* friends = ufi + (size_t)u * CLIP;

    // preload friend ids (uniform per 8-lane group; L1/L2 resident)
    int fid[NT];
    #pragma unroll
    for (int t = 0; t < NT; ++t) {
        const int c = 4 * t + grp;
        fid[t] = (c < CLIP) ? friends[c] : NF;
    }

    const uint4* emb16 = reinterpret_cast<const uint4*>(g_emb_h);  // 8 uint4 per row

    uint4 buf[PF];               // pipeline buffers: 8 halves each

    // ---- prologue
    #pragma unroll
    for (int t = 0; t < PF; ++t)
        buf[t] = emb16[(size_t)fid[t] * 8 + lig];

    float s   = 0.f;             // sum of gate*pd (uniform within 8-lane group)
    int   nfr = 0;
    float ga = 0.f, gb = 0.f;    // gate stash: t==lig, t==lig+8

    // ---- steady state: prefetch t+PF, compute t
    #pragma unroll
    for (int t = 0; t < NT; ++t) {
        const int slot = t % PF;
        const uint4 v = buf[slot];

        if (t + PF < NT)
            buf[slot] = emb16[(size_t)fid[t + PF] * 8 + lig];

        const float2 f0 = __half22float2(*reinterpret_cast<const __half2*>(&v.x));
        const float2 f1 = __half22float2(*reinterpret_cast<const __half2*>(&v.y));
        const float2 f2 = __half22float2(*reinterpret_cast<const __half2*>(&v.z));
        const float2 f3 = __half22float2(*reinterpret_cast<const __half2*>(&v.w));

        float pd = f0.x*iw0.x + f0.y*iw0.y + f1.x*iw0.z + f1.y*iw0.w
                 + f2.x*iw1.x + f2.y*iw1.y + f3.x*iw1.z + f3.y*iw1.w;
        pd += __shfl_xor_sync(0xffffffffu, pd, 4);
        pd += __shfl_xor_sync(0xffffffffu, pd, 2);
        pd += __shfl_xor_sync(0xffffffffu, pd, 1);

        const float gate = 1.f / (1.f + __expf(-(pd + bias)));

        s   += gate * pd;            // padded slots: row NF is zero -> pd==0
        nfr += (fid[t] != NF);

        if (t == lig)     ga = gate;   // covers t=0..7
        if (t == lig + 8) gb = gate;   // covers t=8..12
    }

    // ---- gate output: gp[4*t + grp], coalesced across the warp ----
    if (gidx_out) {
        float* gp = gidx_out + (size_t)warp * CLIP;
        gp[4 * lig + grp] = ga;                          // slots 0..31
        const int c2 = 32 + 4 * lig + grp;               // slots 32..49 (+2 padded)
        if (c2 < CLIP) gp[c2] = gb;
    }

    // ---- combine the 4 groups (values uniform within each group) ----
    s   += __shfl_xor_sync(0xffffffffu, s, 8);
    s   += __shfl_xor_sync(0xffffffffu, s, 16);
    nfr += __shfl_xor_sync(0xffffffffu, nfr, 8);
    nfr += __shfl_xor_sync(0xffffffffu, nfr, 16);

    if (lane == 0) {
        const float logit = s / (float)nfr + bias;   // nfr==0 -> inf/nan, matches ref
        rating_out[warp] = 1.f / (1.f + __expf(-logit));
    }
}

extern "C" void kernel_launch(void* const* d_in, const int* in_sizes, int n_in,
                              void* d_out, int out_size)
{
    const int*   user_indices = (const int*)  d_in[0];
    const int*   item_indices = (const int*)  d_in[1];
    const int*   ufi          = (const int*)  d_in[2];
    const float* emb_user     = (const float*)d_in[3];
    const float* emb_item     = (const float*)d_in[4];
    const float* affine_w     = (const float*)d_in[5];
    const float* affine_b     = (const float*)d_in[6];

    const int B = in_sizes[0];
    float* out = (float*)d_out;

    float* rating = out;
    float* gidx   = (out_size >= B * (1 + CLIP)) ? (out + B) : nullptr;

    // 1) convert emb_user f32 -> f16 shadow table (12.8 MB)
    const int n8 = (NF + 1) * D / 8;                 // 800008 stores of 16 B
    conv_kernel<<<(n8 + 255) / 256, 256>>>(emb_user, n8);

    // 2) main kernel gathers from the fp16 table (half the bytes)
    const int threads = 256;                         // 8 warps/block, 1 warp/row
    const int blocks  = (B * 32 + threads - 1) / threads;
    gmf_kernel<<<blocks, threads>>>(user_indices, item_indices, ufi,
                                    emb_item, affine_w, affine_b,
                                    rating, gidx, B);
}

// round 14
// speedup vs baseline: 1.0576x; 1.0576x over previous
#include <cuda_runtime.h>
#include <cuda_fp16.h>
#include <cstdint>

#define NF   100000
#define CLIP 50
#define D    64
#define NT   13   // friend-slot iterations (4 friends each; 52 slots, 2 padded)
#define PF   5    // software-pipeline depth

// fp16 shadow of emb_user: (NF+1) x 64 halves = 12.8 MB, static device global.
__device__ __half g_emb_h[(size_t)(NF + 1) * D];

// ---- precompute: f32 -> f16 table conversion (8 elems / thread, 16 B stores)
__global__ __launch_bounds__(256)
void conv_kernel(const float* __restrict__ src, int n8)
{
    const int i = blockIdx.x * blockDim.x + threadIdx.x;
    if (i >= n8) return;
    const float4* s = (const float4*)src + 2 * (size_t)i;
    const float4 a = s[0], b = s[1];
    __half2 h0 = __floats2half2_rn(a.x, a.y);
    __half2 h1 = __floats2half2_rn(a.z, a.w);
    __half2 h2 = __floats2half2_rn(b.x, b.y);
    __half2 h3 = __floats2half2_rn(b.z, b.w);
    uint4 p;
    p.x = *reinterpret_cast<unsigned*>(&h0);
    p.y = *reinterpret_cast<unsigned*>(&h1);
    p.z = *reinterpret_cast<unsigned*>(&h2);
    p.w = *reinterpret_cast<unsigned*>(&h3);
    reinterpret_cast<uint4*>(g_emb_h)[i] = p;
}

// 8 lanes per friend (one LDG.128 per friend), 4 friends per warp-iteration.
// logits = sum_c gate_c * pd_c / nfr  (pd_c = dot(fe_c, ie*w) = pre-sigmoid value)
// Dot product in HFMA2; rolling fid queue + PF=5 for ~200 in-flight lines/SM.
__global__ __launch_bounds__(256, 5)
void gmf_kernel(const int*   __restrict__ user_indices,
                const int*   __restrict__ item_indices,
                const int*   __restrict__ ufi,          // [100000, 50]
                const float* __restrict__ emb_item,     // [100000, 64]
                const float* __restrict__ affine_w,     // [64]
                const float* __restrict__ affine_b,     // scalar
                float*       __restrict__ rating_out,   // [B]
                float*       __restrict__ gidx_out,     // [B, 50] or null
                int B)
{
    const int warp = (int)((blockIdx.x * blockDim.x + threadIdx.x) >> 5);
    const int lane = threadIdx.x & 31;
    if (warp >= B) return;

    const int lig = lane & 7;    // lane in 8-lane group
    const int grp = lane >> 3;   // friend-group 0..3

    const int   u    = user_indices[warp];
    const int   it   = item_indices[warp];
    const float bias = *affine_b;

    // lane holds dims [8*lig, 8*lig+8) of (item_emb * w), packed as 4x half2
    __half2 iwh[4];
    {
        const float4* ie = (const float4*)(emb_item + (size_t)it * D);
        const float4* w  = (const float4*)affine_w;
        float4 a = ie[2 * lig],     b0 = w[2 * lig];
        float4 c = ie[2 * lig + 1], d0 = w[2 * lig + 1];
        iwh[0] = __floats2half2_rn(a.x * b0.x, a.y * b0.y);
        iwh[1] = __floats2half2_rn(a.z * b0.z, a.w * b0.w);
        iwh[2] = __floats2half2_rn(c.x * d0.x, c.y * d0.y);
        iwh[3] = __floats2half2_rn(c.z * d0.z, c.w * d0.w);
    }

    const int* friends = ufi + (size_t)u * CLIP;    // 200 B row, L1-resident

    const uint4* emb16 = reinterpret_cast<const uint4*>(g_emb_h);  // 8 uint4 per row

    uint4 buf[PF];               // pipeline data buffers (8 halves each)
    int   fq [PF];               // rolling fid queue

    // ---- prologue: slots 4t+grp for t=0..PF-1 are all < CLIP
    #pragma unroll
    for (int t = 0; t < PF; ++t) {
        fq[t]  = friends[4 * t + grp];
        buf[t] = emb16[(size_t)fq[t] * 8 + lig];
    }

    float s   = 0.f;             // sum of gate*pd (uniform within 8-lane group)
    int   nfr = 0;
    float ga = 0.f, gb = 0.f;    // gate stash: t==lig, t==lig+8

    // ---- steady state: consume slot t%PF, refill for t+PF
    #pragma unroll
    for (int t = 0; t < NT; ++t) {
        const int  slot  = t % PF;
        const uint4 v    = buf[slot];
        const int  myfid = fq[slot];

        if (t + PF < NT) {
            const int c  = 4 * (t + PF) + grp;
            const int nf = (c < CLIP) ? friends[c] : NF;   // L1 hit
            fq[slot]  = nf;
            buf[slot] = emb16[(size_t)nf * 8 + lig];
        }

        // half2 dot: 4 HFMA2 + 1 cvt + 1 add
        __half2 acc = __hmul2(*reinterpret_cast<const __half2*>(&v.x), iwh[0]);
        acc = __hfma2(*reinterpret_cast<const __half2*>(&v.y), iwh[1], acc);
        acc = __hfma2(*reinterpret_cast<const __half2*>(&v.z), iwh[2], acc);
        acc = __hfma2(*reinterpret_cast<const __half2*>(&v.w), iwh[3], acc);
        const float2 af = __half22float2(acc);
        float pd = af.x + af.y;

        pd += __shfl_xor_sync(0xffffffffu, pd, 4);
        pd += __shfl_xor_sync(0xffffffffu, pd, 2);
        pd += __shfl_xor_sync(0xffffffffu, pd, 1);

        const float gate = 1.f / (1.f + __expf(-(pd + bias)));

        s   += gate * pd;            // padded slots: row NF is zero -> pd==0
        nfr += (myfid != NF);

        if (t == lig)     ga = gate;   // covers t=0..7
        if (t == lig + 8) gb = gate;   // covers t=8..12
    }

    // ---- gate output: gp[4*t + grp], coalesced across the warp ----
    if (gidx_out) {
        float* gp = gidx_out + (size_t)warp * CLIP;
        gp[4 * lig + grp] = ga;                          // slots 0..31
        const int c2 = 32 + 4 * lig + grp;               // slots 32..49 (+2 padded)
        if (c2 < CLIP) gp[c2] = gb;
    }

    // ---- combine the 4 groups (values uniform within each group) ----
    s   += __shfl_xor_sync(0xffffffffu, s, 8);
    s   += __shfl_xor_sync(0xffffffffu, s, 16);
    nfr += __shfl_xor_sync(0xffffffffu, nfr, 8);
    nfr += __shfl_xor_sync(0xffffffffu, nfr, 16);

    if (lane == 0) {
        const float logit = s / (float)nfr + bias;   // nfr==0 -> inf/nan, matches ref
        rating_out[warp] = 1.f / (1.f + __expf(-logit));
    }
}

extern "C" void kernel_launch(void* const* d_in, const int* in_sizes, int n_in,
                              void* d_out, int out_size)
{
    const int*   user_indices = (const int*)  d_in[0];
    const int*   item_indices = (const int*)  d_in[1];
    const int*   ufi          = (const int*)  d_in[2];
    const float* emb_user     = (const float*)d_in[3];
    const float* emb_item     = (const float*)d_in[4];
    const float* affine_w     = (const float*)d_in[5];
    const float* affine_b     = (const float*)d_in[6];

    const int B = in_sizes[0];
    float* out = (float*)d_out;

    float* rating = out;
    float* gidx   = (out_size >= B * (1 + CLIP)) ? (out + B) : nullptr;

    // 1) convert emb_user f32 -> f16 shadow table (12.8 MB)
    const int n8 = (NF + 1) * D / 8;                 // 800008 stores of 16 B
    conv_kernel<<<(n8 + 255) / 256, 256>>>(emb_user, n8);

    // 2) main kernel gathers from the fp16 table (half the bytes)
    const int threads = 256;                         // 8 warps/block, 1 warp/row
    const int blocks  = (B * 32 + threads - 1) / threads;
    gmf_kernel<<<blocks, threads>>>(user_indices, item_indices, ufi,
                                    emb_item, affine_w, affine_b,
                                    rating, gidx, B);
}

// round 15
// speedup vs baseline: 1.0591x; 1.0014x over previous
#include <cuda_runtime.h>
#include <cuda_fp16.h>
#include <cstdint>

#define NF   100000
#define CLIP 50
#define D    64
#define NT   7    // iterations: 8 friends each (2 per 8-lane group); 56 slots, 6 padded
#define PF   3    // software-pipeline depth

// fp16 shadow of emb_user: (NF+1) x 64 halves = 12.8 MB, static device global.
__device__ __half g_emb_h[(size_t)(NF + 1) * D];

// ---- precompute: f32 -> f16 table conversion (8 elems / thread, 16 B stores)
__global__ __launch_bounds__(256)
void conv_kernel(const float* __restrict__ src, int n8)
{
    const int i = blockIdx.x * blockDim.x + threadIdx.x;
    if (i >= n8) return;
    const float4* s = (const float4*)src + 2 * (size_t)i;
    const float4 a = s[0], b = s[1];
    __half2 h0 = __floats2half2_rn(a.x, a.y);
    __half2 h1 = __floats2half2_rn(a.z, a.w);
    __half2 h2 = __floats2half2_rn(b.x, b.y);
    __half2 h3 = __floats2half2_rn(b.z, b.w);
    uint4 p;
    p.x = *reinterpret_cast<unsigned*>(&h0);
    p.y = *reinterpret_cast<unsigned*>(&h1);
    p.z = *reinterpret_cast<unsigned*>(&h2);
    p.w = *reinterpret_cast<unsigned*>(&h3);
    reinterpret_cast<uint4*>(g_emb_h)[i] = p;
}

// 8 lanes per friend-pair: each group handles friends (8t+grp) and (8t+4+grp).
// Both partial dots packed in one half2 -> 3 SHFL serve 2 friends.
// logits = sum_c gate_c * pd_c / nfr  (pd_c = dot(fe_c, ie*w) = pre-sigmoid value)
__global__ __launch_bounds__(256, 4)
void gmf_kernel(const int*   __restrict__ user_indices,
                const int*   __restrict__ item_indices,
                const int*   __restrict__ ufi,          // [100000, 50]
                const float* __restrict__ emb_item,     // [100000, 64]
                const float* __restrict__ affine_w,     // [64]
                const float* __restrict__ affine_b,     // scalar
                float*       __restrict__ rating_out,   // [B]
                float*       __restrict__ gidx_out,     // [B, 50] or null
                int B)
{
    const int warp = (int)((blockIdx.x * blockDim.x + threadIdx.x) >> 5);
    const int lane = threadIdx.x & 31;
    if (warp >= B) return;

    const int lig = lane & 7;    // lane in 8-lane group
    const int grp = lane >> 3;   // group 0..3

    const int   u    = user_indices[warp];
    const int   it   = item_indices[warp];
    const float bias = *affine_b;

    // lane holds dims [8*lig, 8*lig+8) of (item_emb * w), packed as 4x half2
    __half2 iwh[4];
    {
        const float4* ie = (const float4*)(emb_item + (size_t)it * D);
        const float4* w  = (const float4*)affine_w;
        float4 a = ie[2 * lig],     b0 = w[2 * lig];
        float4 c = ie[2 * lig + 1], d0 = w[2 * lig + 1];
        iwh[0] = __floats2half2_rn(a.x * b0.x, a.y * b0.y);
        iwh[1] = __floats2half2_rn(a.z * b0.z, a.w * b0.w);
        iwh[2] = __floats2half2_rn(c.x * d0.x, c.y * d0.y);
        iwh[3] = __floats2half2_rn(c.z * d0.z, c.w * d0.w);
    }

    const int* friends = ufi + (size_t)u * CLIP;
    float* gp = gidx_out ? (gidx_out + (size_t)warp * CLIP) : nullptr;

    // preload both fid streams (uniform per group; L1-resident source row)
    int fidA[NT], fidB[NT];
    #pragma unroll
    for (int t = 0; t < NT; ++t) {
        const int cA = 8 * t + grp;          // 0..51
        const int cB = 8 * t + 4 + grp;      // 4..55
        fidA[t] = (cA < CLIP) ? friends[cA] : NF;
        fidB[t] = (cB < CLIP) ? friends[cB] : NF;
    }

    const uint4* emb16 = reinterpret_cast<const uint4*>(g_emb_h);  // 8 uint4 per row

    uint4 bufA[PF], bufB[PF];
    #pragma unroll
    for (int t = 0; t < PF; ++t) {
        bufA[t] = emb16[(size_t)fidA[t] * 8 + lig];
        bufB[t] = emb16[(size_t)fidB[t] * 8 + lig];
    }

    float s   = 0.f;             // sum of gate*pd (uniform within group)
    int   nfr = 0;               // friend count (uniform within group)

    #pragma unroll
    for (int t = 0; t < NT; ++t) {
        const int  slot = t % PF;
        const uint4 vA = bufA[slot];
        const uint4 vB = bufB[slot];

        if (t + PF < NT) {
            bufA[slot] = emb16[(size_t)fidA[t + PF] * 8 + lig];
            bufB[slot] = emb16[(size_t)fidB[t + PF] * 8 + lig];
        }

        // per-lane dots (half2 fma chains, independent A/B)
        __half2 aA = __hmul2(*reinterpret_cast<const __half2*>(&vA.x), iwh[0]);
        aA = __hfma2(*reinterpret_cast<const __half2*>(&vA.y), iwh[1], aA);
        aA = __hfma2(*reinterpret_cast<const __half2*>(&vA.z), iwh[2], aA);
        aA = __hfma2(*reinterpret_cast<const __half2*>(&vA.w), iwh[3], aA);
        __half2 aB = __hmul2(*reinterpret_cast<const __half2*>(&vB.x), iwh[0]);
        aB = __hfma2(*reinterpret_cast<const __half2*>(&vB.y), iwh[1], aB);
        aB = __hfma2(*reinterpret_cast<const __half2*>(&vB.z), iwh[2], aB);
        aB = __hfma2(*reinterpret_cast<const __half2*>(&vB.w), iwh[3], aB);

        // pack {sumA, sumB} into one half2, reduce across the 8-lane group
        __half2 h = __hadd2(__lows2half2(aA, aB), __highs2half2(aA, aB));
        #pragma unroll
        for (int o = 4; o > 0; o >>= 1) {
            unsigned hv = __shfl_xor_sync(0xffffffffu,
                                          *reinterpret_cast<unsigned*>(&h), o);
            h = __hadd2(h, *reinterpret_cast<__half2*>(&hv));
        }
        const float2 pf = __half22float2(h);   // pf.x = pdA, pf.y = pdB

        const float gateA = 1.f / (1.f + __expf(-(pf.x + bias)));
        const float gateB = 1.f / (1.f + __expf(-(pf.y + bias)));

        s   += gateA * pf.x + gateB * pf.y;    // padded slots: pd==0 -> 0
        nfr += (fidA[t] != NF) + (fidB[t] != NF);

        // gate store: 4 lanes/warp (lig==0), 32B contiguous per iteration
        if (gp && lig == 0) {
            const int cA = 8 * t + grp;
            const int cB = cA + 4;
            if (cA < CLIP) gp[cA] = gateA;
            if (cB < CLIP) gp[cB] = gateB;
        }
    }

    // ---- combine the 4 groups (uniform within each 8-lane group) ----
    s   += __shfl_xor_sync(0xffffffffu, s, 8);
    s   += __shfl_xor_sync(0xffffffffu, s, 16);
    nfr += __shfl_xor_sync(0xffffffffu, nfr, 8);
    nfr += __shfl_xor_sync(0xffffffffu, nfr, 16);

    if (lane == 0) {
        const float logit = s / (float)nfr + bias;   // nfr==0 -> inf/nan, matches ref
        rating_out[warp] = 1.f / (1.f + __expf(-logit));
    }
}

extern "C" void kernel_launch(void* const* d_in, const int* in_sizes, int n_in,
                              void* d_out, int out_size)
{
    const int*   user_indices = (const int*)  d_in[0];
    const int*   item_indices = (const int*)  d_in[1];
    const int*   ufi          = (const int*)  d_in[2];
    const float* emb_user     = (const float*)d_in[3];
    const float* emb_item     = (const float*)d_in[4];
    const float* affine_w     = (const float*)d_in[5];
    const float* affine_b     = (const float*)d_in[6];

    const int B = in_sizes[0];
    float* out = (float*)d_out;

    float* rating = out;
    float* gidx   = (out_size >= B * (1 + CLIP)) ? (out + B) : nullptr;

    // 1) convert emb_user f32 -> f16 shadow table (12.8 MB)
    const int n8 = (NF + 1) * D / 8;
    conv_kernel<<<(n8 + 255) / 256, 256>>>(emb_user, n8);

    // 2) main kernel gathers from the fp16 table
    const int threads = 256;                 // 8 warps/block, 1 warp per batch row
    const int blocks  = (B * 32 + threads - 1) / threads;
    gmf_kernel<<<blocks, threads>>>(user_indices, item_indices, ufi,
                                    emb_item, affine_w, affine_b,
                                    rating, gidx, B);
}